// round 9
// baseline (speedup 1.0000x reference)
#include <cuda_runtime.h>
#include <cuda_bf16.h>
#include <cstdint>

#define TT   2048
#define NTHR 512

// row strides in bf16 elems; (stride/2) mod 32 == 4 -> conflict-free fragment access
constexpr int KA  = 136;
constexpr int KB1 = 72;
constexpr int KB2 = 136;

constexpr uint32_t A_LO   = 16u * KA * 2;             // lo tile offset within group A region
constexpr uint32_t A_GRP  = 2u * A_LO;                // 8704 B per group (hi + lo)
constexpr uint32_t B1H = 4u * A_GRP;                  // 34816
constexpr uint32_t B1L = B1H + 208u * KB1 * 2;
constexpr uint32_t B2H = B1L + 208u * KB1 * 2;
constexpr uint32_t B2L = B2H + 208u * KB2 * 2;
constexpr uint32_t SCRATCH = B2L + 208u * KB2 * 2;    // 207872: [4 grp][4 role][16 row] f32
constexpr uint32_t SMEM_BYTES = SCRATCH + 1024;       // 208896

// m16n8k16 row.col bf16 HMMA, fp32 accumulate (family-target safe)
__device__ __forceinline__ void mma4(float* d,
                                     uint32_t a0, uint32_t a1, uint32_t a2, uint32_t a3,
                                     uint32_t b0, uint32_t b1) {
    asm volatile(
        "mma.sync.aligned.m16n8k16.row.col.f32.bf16.bf16.f32 "
        "{%0,%1,%2,%3}, {%4,%5,%6,%7}, {%8,%9}, {%0,%1,%2,%3};"
        : "+f"(d[0]), "+f"(d[1]), "+f"(d[2]), "+f"(d[3])
        : "r"(a0), "r"(a1), "r"(a2), "r"(a3), "r"(b0), "r"(b1));
}

__device__ __forceinline__ void grpbar(int grp) {
    asm volatile("bar.sync %0, 128;" :: "r"(grp + 1) : "memory");
}

// precise activations (~2ulp): ex2.approx + rcp.approx
__device__ __forceinline__ float fsig(float x) {
    return __fdividef(1.0f, 1.0f + __expf(-x));
}
__device__ __forceinline__ float ftanh_(float x) {
    x = fminf(fmaxf(x, -15.0f), 15.0f);
    float e = __expf(-2.0f * x);
    return __fdividef(1.0f - e, 1.0f + e);
}
__device__ __forceinline__ void bsplit(float v, __nv_bfloat16& h, __nv_bfloat16& l) {
    h = __float2bfloat16(v);
    l = __float2bfloat16(v - __bfloat162float(h));
}

__global__ void __launch_bounds__(NTHR, 1) lstm_hmma4_kernel(
    const float* __restrict__ input,
    const float* __restrict__ W_ih1, const float* __restrict__ W_hh1,
    const float* __restrict__ b_ih1, const float* __restrict__ b_hh1,
    const float* __restrict__ W_ih2, const float* __restrict__ W_hh2,
    const float* __restrict__ b_ih2, const float* __restrict__ b_hh2,
    const float* __restrict__ W_lin, const float* __restrict__ b_lin,
    float* __restrict__ out)
{
    extern __shared__ char smc[];
    const int tid  = threadIdx.x;
    const int warp = tid >> 5, lane = tid & 31;
    const int grp  = warp >> 2, role = warp & 3;
    const int cc = lane & 3, gg = lane >> 2;

    // ---- zero all smem ----
    for (uint32_t i = tid * 16; i < SMEM_BYTES; i += NTHR * 16)
        *(uint4*)(smc + i) = make_uint4(0, 0, 0, 0);
    __syncthreads();

    // gate-row -> n mapping: i->2j, f->2j+1, g->104+2j, o->105+2j
    // ---- stage B1 [208][72] hi/lo: k0-50 Whh1, k52 bias1, k53 Wih1 ----
    for (int idx = tid; idx < 204 * 53; idx += NTHR) {
        int R = idx / 53, kk = idx - R * 53;
        int q = R / 51, j = R - q * 51;
        int n = (q < 2) ? (2 * j + q) : (104 + 2 * j + (q - 2));
        float v; int col;
        if (kk < 51)       { v = W_hh1[R * 51 + kk];      col = kk; }
        else if (kk == 51) { v = b_ih1[R] + b_hh1[R];     col = 52; }
        else               { v = W_ih1[R];                col = 53; }
        __nv_bfloat16 h, l; bsplit(v, h, l);
        *(__nv_bfloat16*)(smc + B1H + (n * KB1 + col) * 2) = h;
        *(__nv_bfloat16*)(smc + B1L + (n * KB1 + col) * 2) = l;
    }
    // ---- stage B2 [208][136] hi/lo: k0-50 Wih2, k52 bias2, k56-106 Whh2 ----
    for (int idx = tid; idx < 204 * 103; idx += NTHR) {
        int R = idx / 103, kk = idx - R * 103;
        int q = R / 51, j = R - q * 51;
        int n = (q < 2) ? (2 * j + q) : (104 + 2 * j + (q - 2));
        float v; int col;
        if (kk < 51)       { v = W_ih2[R * 51 + kk];        col = kk; }
        else if (kk == 51) { v = b_ih2[R] + b_hh2[R];       col = 52; }
        else               { v = W_hh2[R * 51 + (kk - 52)]; col = 56 + (kk - 52); }
        __nv_bfloat16 h, l; bsplit(v, h, l);
        *(__nv_bfloat16*)(smc + B2H + (n * KB2 + col) * 2) = h;
        *(__nv_bfloat16*)(smc + B2L + (n * KB2 + col) * 2) = l;
    }
    // ---- A init: constant-one col 52 (hi), x(0) col 53 (hi+lo) ----
    if (tid < 64) {
        int p = tid >> 4, rl = tid & 15;
        uint32_t ab = p * A_GRP;
        *(__nv_bfloat16*)(smc + ab + (rl * KA + 52) * 2) = __float2bfloat16(1.0f);
        float x0 = input[((long)blockIdx.x * 64 + tid) * TT];
        __nv_bfloat16 h, l; bsplit(x0, h, l);
        *(__nv_bfloat16*)(smc + ab +        (rl * KA + 53) * 2) = h;
        *(__nv_bfloat16*)(smc + ab + A_LO + (rl * KA + 53) * 2) = l;
    }
    __syncthreads();

    // ---- per-thread fragment bases ----
    const uint32_t aH  = grp * A_GRP + (gg * KA + 2 * cc) * 2;
    const uint32_t aL  = aH + A_LO;
    const uint32_t b1h = B1H + (gg * KB1 + 2 * cc) * 2;
    const uint32_t b1l = B1L + (gg * KB1 + 2 * cc) * 2;
    const uint32_t b2h = B2H + (gg * KB2 + 2 * cc) * 2;
    const uint32_t b2l = B2L + (gg * KB2 + 2 * cc) * 2;
    const uint32_t whA = grp * A_GRP + (gg * KA) * 2;    // h-write base, row gg
    float* const scr   = (float*)(smc + SCRATCH);

    // gate-tile 4-way split with shared boundary tiles: role r -> jt 3r..3r+3
    // (jt 3,6,9 duplicated across adjacent roles; higher role zeroes its wl[0])
    const int jt0 = 3 * role;

    float wl[4];
#pragma unroll
    for (int q = 0; q < 4; q++) {
        int j = 4 * (jt0 + q) + cc;
        wl[q] = (j < 51) ? W_lin[j] : 0.f;
    }
    if (role > 0) wl[0] = 0.f;   // boundary tile counted by lower role
    const float blin = b_lin[0];

    float c1a[4], c1b[4], c2a[4], c2b[4];
#pragma unroll
    for (int q = 0; q < 4; q++) { c1a[q] = c1b[q] = c2a[q] = c2b[q] = 0.f; }

    const long rg0 = (long)blockIdx.x * 64 + grp * 16 + gg;   // D rows: rg0, rg0+8

    float D[8][4];

#pragma unroll 1
    for (int t = 0; t < TT; t++) {
        // prefetch x(t+1) (role3 stages x)
        float xn0 = 0.f, xn1 = 0.f;
        if (role == 3 && cc == 0 && t + 1 < TT) {
            xn0 = input[rg0 * TT + t + 1];
            xn1 = input[(rg0 + 8) * TT + t + 1];
        }

        // ================= layer 1 MMA: ks 0-3 (A cols 0-63) =================
#pragma unroll
        for (int nt = 0; nt < 8; nt++) { D[nt][0] = 0.f; D[nt][1] = 0.f; D[nt][2] = 0.f; D[nt][3] = 0.f; }
#pragma unroll
        for (int ks = 0; ks < 4; ks++) {
            const uint32_t ah0 = *(const uint32_t*)(smc + aH + ks * 32);
            const uint32_t ah1 = *(const uint32_t*)(smc + aH + 2176 + ks * 32);
            const uint32_t ah2 = *(const uint32_t*)(smc + aH + 16 + ks * 32);
            const uint32_t ah3 = *(const uint32_t*)(smc + aH + 2192 + ks * 32);
            const uint32_t al0 = *(const uint32_t*)(smc + aL + ks * 32);
            const uint32_t al1 = *(const uint32_t*)(smc + aL + 2176 + ks * 32);
            const uint32_t al2 = *(const uint32_t*)(smc + aL + 16 + ks * 32);
            const uint32_t al3 = *(const uint32_t*)(smc + aL + 2192 + ks * 32);
#pragma unroll
            for (int q = 0; q < 4; q++) {
                const uint32_t boI = (uint32_t)(jt0 + q) * 1152 + ks * 32;        // i/f tile
                const uint32_t boG = (uint32_t)(13 + jt0 + q) * 1152 + ks * 32;   // g/o tile
                uint32_t bh0 = *(const uint32_t*)(smc + b1h + boI);
                uint32_t bh1 = *(const uint32_t*)(smc + b1h + boI + 16);
                mma4(D[q], ah0, ah1, ah2, ah3, bh0, bh1);
                mma4(D[q], al0, al1, al2, al3, bh0, bh1);
                uint32_t bl0 = *(const uint32_t*)(smc + b1l + boI);
                uint32_t bl1 = *(const uint32_t*)(smc + b1l + boI + 16);
                mma4(D[q], ah0, ah1, ah2, ah3, bl0, bl1);
                bh0 = *(const uint32_t*)(smc + b1h + boG);
                bh1 = *(const uint32_t*)(smc + b1h + boG + 16);
                mma4(D[4 + q], ah0, ah1, ah2, ah3, bh0, bh1);
                mma4(D[4 + q], al0, al1, al2, al3, bh0, bh1);
                bl0 = *(const uint32_t*)(smc + b1l + boG);
                bl1 = *(const uint32_t*)(smc + b1l + boG + 16);
                mma4(D[4 + q], ah0, ah1, ah2, ah3, bl0, bl1);
            }
        }
        grpbar(grp);   // MMA1 reads done before h1 overwrite

        // ================= epilogue 1: c1/h1, write h1 cols j =================
#pragma unroll
        for (int q = 0; q < 4; q++) {
            float i0 = D[q][0], f0 = D[q][1], i1 = D[q][2], f1 = D[q][3];
            float g0 = D[4 + q][0], o0 = D[4 + q][1], g1 = D[4 + q][2], o1 = D[4 + q][3];
            float cn0 = fmaf(fsig(f0), c1a[q], fsig(i0) * ftanh_(g0));
            float cn1 = fmaf(fsig(f1), c1b[q], fsig(i1) * ftanh_(g1));
            c1a[q] = cn0; c1b[q] = cn1;
            float h0  = fsig(o0) * ftanh_(cn0);
            float h1v = fsig(o1) * ftanh_(cn1);
            const int j2 = (4 * (jt0 + q) + cc) * 2;
            __nv_bfloat16 bh, bl;
            bsplit(h0, bh, bl);
            *(__nv_bfloat16*)(smc + whA + j2)        = bh;
            *(__nv_bfloat16*)(smc + whA + A_LO + j2) = bl;
            bsplit(h1v, bh, bl);
            *(__nv_bfloat16*)(smc + whA + 2176 + j2)        = bh;
            *(__nv_bfloat16*)(smc + whA + A_LO + 2176 + j2) = bl;
        }
        grpbar(grp);   // h1(t) visible to all 4 warps

        // ================= layer 2 MMA: ks 0-6 (A cols 0-111) =================
#pragma unroll
        for (int nt = 0; nt < 8; nt++) { D[nt][0] = 0.f; D[nt][1] = 0.f; D[nt][2] = 0.f; D[nt][3] = 0.f; }
#pragma unroll
        for (int ks = 0; ks < 7; ks++) {
            const uint32_t ah0 = *(const uint32_t*)(smc + aH + ks * 32);
            const uint32_t ah1 = *(const uint32_t*)(smc + aH + 2176 + ks * 32);
            const uint32_t ah2 = *(const uint32_t*)(smc + aH + 16 + ks * 32);
            const uint32_t ah3 = *(const uint32_t*)(smc + aH + 2192 + ks * 32);
            const uint32_t al0 = *(const uint32_t*)(smc + aL + ks * 32);
            const uint32_t al1 = *(const uint32_t*)(smc + aL + 2176 + ks * 32);
            const uint32_t al2 = *(const uint32_t*)(smc + aL + 16 + ks * 32);
            const uint32_t al3 = *(const uint32_t*)(smc + aL + 2192 + ks * 32);
#pragma unroll
            for (int q = 0; q < 4; q++) {
                const uint32_t boI = (uint32_t)(jt0 + q) * 2176 + ks * 32;
                const uint32_t boG = (uint32_t)(13 + jt0 + q) * 2176 + ks * 32;
                uint32_t bh0 = *(const uint32_t*)(smc + b2h + boI);
                uint32_t bh1 = *(const uint32_t*)(smc + b2h + boI + 16);
                mma4(D[q], ah0, ah1, ah2, ah3, bh0, bh1);
                mma4(D[q], al0, al1, al2, al3, bh0, bh1);
                uint32_t bl0 = *(const uint32_t*)(smc + b2l + boI);
                uint32_t bl1 = *(const uint32_t*)(smc + b2l + boI + 16);
                mma4(D[q], ah0, ah1, ah2, ah3, bl0, bl1);
                bh0 = *(const uint32_t*)(smc + b2h + boG);
                bh1 = *(const uint32_t*)(smc + b2h + boG + 16);
                mma4(D[4 + q], ah0, ah1, ah2, ah3, bh0, bh1);
                mma4(D[4 + q], al0, al1, al2, al3, bh0, bh1);
                bl0 = *(const uint32_t*)(smc + b2l + boG);
                bl1 = *(const uint32_t*)(smc + b2l + boG + 16);
                mma4(D[4 + q], ah0, ah1, ah2, ah3, bl0, bl1);
            }
        }
        grpbar(grp);   // MMA2 reads done before h2 overwrite

        // ========= epilogue 2: c2/h2, write h2 cols 56+j, partial out =========
        float s0 = 0.f, s1 = 0.f;
#pragma unroll
        for (int q = 0; q < 4; q++) {
            float i0 = D[q][0], f0 = D[q][1], i1 = D[q][2], f1 = D[q][3];
            float g0 = D[4 + q][0], o0 = D[4 + q][1], g1 = D[4 + q][2], o1 = D[4 + q][3];
            float cn0 = fmaf(fsig(f0), c2a[q], fsig(i0) * ftanh_(g0));
            float cn1 = fmaf(fsig(f1), c2b[q], fsig(i1) * ftanh_(g1));
            c2a[q] = cn0; c2b[q] = cn1;
            float h0  = fsig(o0) * ftanh_(cn0);
            float h1v = fsig(o1) * ftanh_(cn1);
            s0 = fmaf(wl[q], h0, s0);
            s1 = fmaf(wl[q], h1v, s1);
            const int j2 = (56 + 4 * (jt0 + q) + cc) * 2;
            __nv_bfloat16 bh, bl;
            bsplit(h0, bh, bl);
            *(__nv_bfloat16*)(smc + whA + j2)        = bh;
            *(__nv_bfloat16*)(smc + whA + A_LO + j2) = bl;
            bsplit(h1v, bh, bl);
            *(__nv_bfloat16*)(smc + whA + 2176 + j2)        = bh;
            *(__nv_bfloat16*)(smc + whA + A_LO + 2176 + j2) = bl;
        }
        // quad-reduce partial, stash to scratch; role3 stages x(t+1)
        s0 += __shfl_xor_sync(0xffffffffu, s0, 1);
        s0 += __shfl_xor_sync(0xffffffffu, s0, 2);
        s1 += __shfl_xor_sync(0xffffffffu, s1, 1);
        s1 += __shfl_xor_sync(0xffffffffu, s1, 2);
        if (cc == 0) {
            scr[(grp * 4 + role) * 16 + gg]     = s0;
            scr[(grp * 4 + role) * 16 + 8 + gg] = s1;
            if (role == 3) {
                __nv_bfloat16 bh, bl;
                bsplit(xn0, bh, bl);
                *(__nv_bfloat16*)(smc + whA + 53 * 2)        = bh;
                *(__nv_bfloat16*)(smc + whA + A_LO + 53 * 2) = bl;
                bsplit(xn1, bh, bl);
                *(__nv_bfloat16*)(smc + whA + 2176 + 53 * 2)        = bh;
                *(__nv_bfloat16*)(smc + whA + A_LO + 2176 + 53 * 2) = bl;
            }
        }
        grpbar(grp);   // h2(t), x(t+1), partials visible

        if (role == 0 && cc == 0) {
            float o0 = blin, o1 = blin;
#pragma unroll
            for (int r = 0; r < 4; r++) {
                o0 += scr[(grp * 4 + r) * 16 + gg];
                o1 += scr[(grp * 4 + r) * 16 + 8 + gg];
            }
            out[rg0 * TT + t]       = o0;
            out[(rg0 + 8) * TT + t] = o1;
        }
    }
}

extern "C" void kernel_launch(void* const* d_in, const int* in_sizes, int n_in,
                              void* d_out, int out_size) {
    const float* input = (const float*)d_in[0];
    const float* W_ih1 = (const float*)d_in[1];
    const float* W_hh1 = (const float*)d_in[2];
    const float* b_ih1 = (const float*)d_in[3];
    const float* b_hh1 = (const float*)d_in[4];
    const float* W_ih2 = (const float*)d_in[5];
    const float* W_hh2 = (const float*)d_in[6];
    const float* b_ih2 = (const float*)d_in[7];
    const float* b_hh2 = (const float*)d_in[8];
    const float* W_lin = (const float*)d_in[9];
    const float* b_lin = (const float*)d_in[10];
    float* out = (float*)d_out;

    const int B = in_sizes[0] / TT;        // 8192
    const int grid = B / 64;               // 128 persistent CTAs (64 rows each)

    cudaFuncSetAttribute(lstm_hmma4_kernel,
                         cudaFuncAttributeMaxDynamicSharedMemorySize, SMEM_BYTES);

    lstm_hmma4_kernel<<<grid, NTHR, SMEM_BYTES>>>(
        input, W_ih1, W_hh1, b_ih1, b_hh1,
        W_ih2, W_hh2, b_ih2, b_hh2, W_lin, b_lin, out);
}